// round 11
// baseline (speedup 1.0000x reference)
#include <cuda_runtime.h>
#include <cuda_fp16.h>
#include <cstdint>
#include <math.h>

// Problem shape (fixed by reference): B=128, T=2048, H=128
#define B_DIM 128
#define T_DIM 2048
#define H_DIM 128
#define BT (B_DIM * T_DIM)

#define SW128(off) ((off) ^ (((off) >> 3) & 0x70))

__device__ __forceinline__ uint32_t smem_to_u32(const void* p) {
    uint32_t a;
    asm("{ .reg .u64 t; cvta.to.shared.u64 t, %1; cvt.u32.u64 %0, t; }"
        : "=r"(a) : "l"(p));
    return a;
}

__device__ __forceinline__ void ldsm4(uint32_t* r, uint32_t addr) {
    asm volatile("ldmatrix.sync.aligned.m8n8.x4.shared.b16 {%0,%1,%2,%3}, [%4];"
                 : "=r"(r[0]), "=r"(r[1]), "=r"(r[2]), "=r"(r[3]) : "r"(addr));
}

// mma m16n8k16 row.col f32.f16.f16.f32
__device__ __forceinline__ void mma_f16(float* c, const uint32_t* a,
                                        uint32_t b0, uint32_t b1) {
    asm volatile(
        "mma.sync.aligned.m16n8k16.row.col.f32.f16.f16.f32 "
        "{%0,%1,%2,%3}, {%4,%5,%6,%7}, {%8,%9}, {%0,%1,%2,%3};"
        : "+f"(c[0]), "+f"(c[1]), "+f"(c[2]), "+f"(c[3])
        : "r"(a[0]), "r"(a[1]), "r"(a[2]), "r"(a[3]), "r"(b0), "r"(b1));
}

__device__ __forceinline__ void cp16(uint32_t dst, const void* src) {
    asm volatile("cp.async.cg.shared.global [%0], [%1], 16;"
                 :: "r"(dst), "l"(src));
}
#define CP_COMMIT() asm volatile("cp.async.commit_group;" ::: "memory")
#define CP_WAIT0()  asm volatile("cp.async.wait_group 0;" ::: "memory")

__device__ __forceinline__ float tanh_fast(float z) {
    const float ex = __expf(2.f * z);
    return 1.f - __fdividef(2.f, ex + 1.f);
}

// ---------------------------------------------------------------------------
// Pre-converted weights: 4 K-chunks; each = one SW128 fp16 tile [128 o][64 k].
// g_Hp16: fp16 mirror of H_pos (written by energy kernel, read by context).
// ---------------------------------------------------------------------------
__device__ __align__(16) unsigned char g_Wimg[4 * 16384];
__device__ float g_ctxp[8 * B_DIM * H_DIM];                   // context partials
__device__ __align__(16) __half g_Hp16[(size_t)BT * H_DIM];   // 64 MB scratch

__global__ __launch_bounds__(256) void wconv_kernel(
    const float* __restrict__ Wh, const float* __restrict__ Wd)
{
    const int idx = blockIdx.x * 256 + threadIdx.x;   // 32768 total
    const int ch  = idx >> 13;
    const int rem = idx & 8191;
    const int o   = rem >> 6;
    const int kc  = rem & 63;
    const float* src = (ch < 2) ? Wh : Wd;
    const float x = src[o * 128 + (ch & 1) * 64 + kc];
    const uint32_t sw = SW128((uint32_t)(o * 128 + kc * 2));
    *(__half*)(g_Wimg + ch * 16384 + sw) = __float2half_rn(x);
}

// ---------------------------------------------------------------------------
// Energy kernel (HMMA fp16, single pass, cp.async-pipelined staging).
// CTA = 128 threads (4 warps), M-tile 128 x N=128, K=256 in 4 chunks of 64.
// Raw fp32 X chunk + next B tile land via cp.async during the current chunk's
// MMA phase; only the smem->smem fp16 conversion is exposed.
// ---------------------------------------------------------------------------
#define A_X   1024
#define B_W0  (1024 + 16384)
#define B_W1  (1024 + 32768)
#define RAWB  (1024 + 49152)          // 128 rows x 272 B (64 floats + 16B pad)
#define ENERGY_SMEM (1024 + 49152 + 34816 + 1024)

__global__ __launch_bounds__(128) void energy_hmma_kernel(
    const float* __restrict__ Hp, const float* __restrict__ Hd,
    const float* __restrict__ Wa, float* __restrict__ energy)
{
    extern __shared__ char dsmem[];
    const uint32_t raw  = smem_to_u32(dsmem);
    const uint32_t base = (raw + 1023) & ~1023u;
    char* basep = dsmem + (base - raw);

    float* esum = (float*)(basep);          // [0,512): per-row energy
    float* wa_s = (float*)(basep + 512);    // [512,1024): W_a copy

    const int tid  = threadIdx.x;
    const int lane = tid & 31;
    const int wid  = tid >> 5;
    const int wy   = wid >> 1;              // row half
    const int wx   = wid & 1;               // col half
    const int row0 = blockIdx.x * 128;

    wa_s[tid & 127] = Wa[tid & 127];

    const int q  = lane >> 3;
    const int l7 = lane & 7;
    const uint32_t offA0 = (uint32_t)((wy * 64 + l7 + (q & 1) * 8) * 128 + (q >> 1) * 16);
    const uint32_t offB0 = (uint32_t)((wx * 64 + l7 + (q >> 1) * 8) * 128 + (q & 1) * 16);
    const uint32_t baseA = base + A_X;
    const uint32_t rawb  = base + RAWB;

    float acc[4][8][4];
    #pragma unroll
    for (int mt = 0; mt < 4; ++mt)
        #pragma unroll
        for (int nt = 0; nt < 8; ++nt)
            #pragma unroll
            for (int j = 0; j < 4; ++j) acc[mt][nt][j] = 0.f;

    // Stage raw X chunk + B tile for chunk CH via cp.async (one group).
    #define STAGE(CH) do {                                                    \
        const float* xs = (((CH) < 2) ? Hp : Hd) + (((CH) & 1) * 64);         \
        _Pragma("unroll")                                                     \
        for (int j = 0; j < 16; ++j) {                                        \
            const int idx = j * 128 + tid;                                    \
            const int r   = idx >> 4;                                         \
            const int seg = idx & 15;                                         \
            cp16(rawb + r * 272 + seg * 16,                                   \
                 xs + (((size_t)(row0 + r)) << 7) + seg * 4);                 \
        }                                                                     \
        const uint32_t bdst = base + (((CH) & 1) ? B_W1 : B_W0);              \
        const char* ws = (const char*)(g_Wimg + (size_t)(CH) * 16384);        \
        _Pragma("unroll")                                                     \
        for (int j = 0; j < 8; ++j) {                                         \
            const int i = j * 128 + tid;                                      \
            cp16(bdst + i * 16, ws + i * 16);                                 \
        }                                                                     \
        CP_COMMIT();                                                          \
    } while (0)

    // Convert raw fp32 -> A fp16 (SW128); mirror H_pos chunks to gmem.
    #define CONVERT(CH) do {                                                  \
        const int r = tid;                                                    \
        _Pragma("unroll")                                                     \
        for (int gg = 0; gg < 16; ++gg) {                                     \
            const int g = (gg + 2 * (tid & 7)) & 15;                          \
            const float4 v = *(const float4*)(basep + RAWB + r * 272 + g * 16); \
            const __half2 h0 = __floats2half2_rn(v.x, v.y);                   \
            const __half2 h1 = __floats2half2_rn(v.z, v.w);                   \
            uint2 hi2;                                                        \
            hi2.x = *(const uint32_t*)&h0;  hi2.y = *(const uint32_t*)&h1;    \
            const uint32_t sw = SW128((uint32_t)(r * 128 + g * 8));           \
            *(uint2*)(basep + A_X + sw) = hi2;                                \
            if ((CH) < 2)                                                     \
                *(uint2*)(g_Hp16 + ((size_t)(row0 + r) << 7)                  \
                          + ((CH) & 1) * 64 + g * 4) = hi2;                   \
        }                                                                     \
    } while (0)

    // ---- prologue ----
    STAGE(0);
    CP_WAIT0();
    __syncthreads();
    CONVERT(0);
    __syncthreads();
    STAGE(1);

    #pragma unroll 1
    for (int ch = 0; ch < 4; ++ch) {
        const uint32_t baseB = base + ((ch & 1) ? B_W1 : B_W0);

        // ---- compute chunk ch: 4 k-steps of 16 ----
        #pragma unroll 1
        for (int ks = 0; ks < 4; ++ks) {
            const uint32_t ks32 = ks * 32;
            uint32_t br[4][4], a[4][4];
            #pragma unroll
            for (int p = 0; p < 4; ++p)
                ldsm4(br[p], baseB + SW128(offB0 + p * 2048 + ks32));
            #pragma unroll
            for (int mt = 0; mt < 4; ++mt)
                ldsm4(a[mt], baseA + SW128(offA0 + mt * 2048 + ks32));
            #pragma unroll
            for (int mt = 0; mt < 4; ++mt)
                #pragma unroll
                for (int nt = 0; nt < 8; ++nt)
                    mma_f16(acc[mt][nt], a[mt],
                            br[nt >> 1][(nt & 1) * 2], br[nt >> 1][(nt & 1) * 2 + 1]);
        }

        // ---- stage next ----
        if (ch < 3) {
            CP_WAIT0();          // raw(ch+1) + B(ch+1) landed during compute
            __syncthreads();     // compute(ch) done; A safe to overwrite
            if (ch == 0) CONVERT(1);
            else if (ch == 1) CONVERT(2);
            else CONVERT(3);     // exposed: smem->smem fp16 convert (+mirror STG)
            __syncthreads();     // A visible; raw buffer free
            if (ch == 0) STAGE(2);
            else if (ch == 1) STAGE(3);  // lands during compute(ch+1)
        }
    }

    // ---- epilogue ----
    float wa_r[16];
    #pragma unroll
    for (int nt = 0; nt < 8; ++nt) {
        wa_r[nt * 2 + 0] = wa_s[wx * 64 + nt * 8 + (lane & 3) * 2 + 0];
        wa_r[nt * 2 + 1] = wa_s[wx * 64 + nt * 8 + (lane & 3) * 2 + 1];
    }
    __syncthreads();
    esum[tid & 127] = 0.f;
    __syncthreads();

    #pragma unroll
    for (int mt = 0; mt < 4; ++mt) {
        #pragma unroll
        for (int half = 0; half < 2; ++half) {
            float p = 0.f;
            #pragma unroll
            for (int nt = 0; nt < 8; ++nt) {
                p += wa_r[nt * 2 + 0] * tanh_fast(acc[mt][nt][half * 2 + 0]);
                p += wa_r[nt * 2 + 1] * tanh_fast(acc[mt][nt][half * 2 + 1]);
            }
            p += __shfl_xor_sync(0xffffffffu, p, 1);
            p += __shfl_xor_sync(0xffffffffu, p, 2);
            if ((lane & 3) == 0)
                atomicAdd(&esum[wy * 64 + mt * 16 + half * 8 + (lane >> 2)], p);
        }
    }
    __syncthreads();
    energy[row0 + tid] = esum[tid];
}

// ---------------------------------------------------------------------------
// Softmax: 1024 threads, 2 elems/thread, register-resident, shuffle reductions.
// ---------------------------------------------------------------------------
__device__ __forceinline__ float warp_max(float v) {
    #pragma unroll
    for (int m = 16; m > 0; m >>= 1)
        v = fmaxf(v, __shfl_xor_sync(0xffffffffu, v, m));
    return v;
}
__device__ __forceinline__ float warp_sum(float v) {
    #pragma unroll
    for (int m = 16; m > 0; m >>= 1)
        v += __shfl_xor_sync(0xffffffffu, v, m);
    return v;
}
__device__ __forceinline__ float block_red(float v, float* red, int tid, bool is_max) {
    v = is_max ? warp_max(v) : warp_sum(v);
    if ((tid & 31) == 0) red[tid >> 5] = v;
    __syncthreads();
    if (tid < 32) {
        float w = red[tid];
        w = is_max ? warp_max(w) : warp_sum(w);
        if (tid == 0) red[0] = w;
    }
    __syncthreads();
    float r = red[0];
    __syncthreads();
    return r;
}

__global__ __launch_bounds__(1024) void softmax_kernel(
    const float* __restrict__ acc_w, const float* __restrict__ ba_p,
    const float* __restrict__ beta_p, float* __restrict__ alpha)
{
    const int b = blockIdx.x;
    const int tid = threadIdx.x;
    __shared__ float red[32];

    const float* aw = acc_w + (size_t)b * T_DIM;
    float* al = alpha + (size_t)b * T_DIM;

    const float a0 = aw[tid], a1 = aw[tid + 1024];
    const float e0 = al[tid], e1 = al[tid + 1024];

    const float denom = fmaxf(block_red(fmaxf(a0, a1), red, tid, true), 1e-6f);

    const float beta = *beta_p;
    const float bpos = fmaxf(beta, 0.f) + log1pf(expf(-fabsf(beta)));
    const float ba = *ba_p;
    const float inv_d = bpos / denom;

    const float s0 = (e0 + ba) * (1.f + inv_d * a0);
    const float s1 = (e1 + ba) * (1.f + inv_d * a1);

    const float smax = block_red(fmaxf(s0, s1), red, tid, true);
    const float p0 = expf(s0 - smax);
    const float p1 = expf(s1 - smax);
    const float inv = 1.f / block_red(p0 + p1, red, tid, false);

    al[tid]        = p0 * inv;
    al[tid + 1024] = p1 * inv;
}

// ---------------------------------------------------------------------------
// Context stage 1: grid = B*8 (b x 8 T-parts), 256 threads = 8 warps.
// Reads the fp16 H_pos mirror (half the DRAM traffic of fp32).
// ---------------------------------------------------------------------------
__global__ __launch_bounds__(256) void context_part_kernel(
    const float* __restrict__ alpha)
{
    const int bid  = blockIdx.x;
    const int b    = bid >> 3;
    const int part = bid & 7;
    const int tid  = threadIdx.x;
    const int lane = tid & 31;
    const int w    = tid >> 5;            // 0..7

    const float* al = alpha + (size_t)b * T_DIM;
    const __half* hp = g_Hp16 + ((size_t)b * T_DIM) * H_DIM + lane * 4;

    const int t0 = part * 256 + w * 32;
    float4 acc = make_float4(0.f, 0.f, 0.f, 0.f);
    #pragma unroll 8
    for (int t = 0; t < 32; ++t) {
        const float a = al[t0 + t];
        const uint2 u = *(const uint2*)(hp + (size_t)(t0 + t) * H_DIM);
        const float2 f0 = __half22float2(*(const __half2*)&u.x);
        const float2 f1 = __half22float2(*(const __half2*)&u.y);
        acc.x += a * f0.x; acc.y += a * f0.y;
        acc.z += a * f1.x; acc.w += a * f1.y;
    }

    __shared__ float cbuf[8 * 128];
    *(float4*)&cbuf[w * 128 + lane * 4] = acc;
    __syncthreads();

    if (tid < 128) {
        float s = 0.f;
        #pragma unroll
        for (int j = 0; j < 8; ++j) s += cbuf[j * 128 + tid];
        g_ctxp[(part * B_DIM + b) * H_DIM + tid] = s;
    }
}

__global__ __launch_bounds__(1024) void context_reduce_kernel(float* __restrict__ ctx)
{
    const int i = blockIdx.x * 1024 + threadIdx.x;   // 16384 total
    float s = 0.f;
    #pragma unroll
    for (int p = 0; p < 8; ++p) s += g_ctxp[p * 16384 + i];
    ctx[i] = s;
}

// ---------------------------------------------------------------------------
// Launch. Inputs per metadata order:
//   0 H_pos, 1 H_dyn, 2 acc_w, 3 W_h, 4 W_d, 5 W_a, 6 b_a, 7 beta
// Output: context [B,H] then alpha [B,T]. Energy staged in the alpha region.
// ---------------------------------------------------------------------------
extern "C" void kernel_launch(void* const* d_in, const int* in_sizes, int n_in,
                              void* d_out, int out_size)
{
    const float* Hp   = (const float*)d_in[0];
    const float* Hd   = (const float*)d_in[1];
    const float* accw = (const float*)d_in[2];
    const float* Wh   = (const float*)d_in[3];
    const float* Wd   = (const float*)d_in[4];
    const float* Wa   = (const float*)d_in[5];
    const float* ba   = (const float*)d_in[6];
    const float* beta = (const float*)d_in[7];

    float* out   = (float*)d_out;
    float* ctx   = out;                    // [B, H]
    float* alpha = out + B_DIM * H_DIM;    // [B, T]

    cudaFuncSetAttribute(energy_hmma_kernel,
                         cudaFuncAttributeMaxDynamicSharedMemorySize, ENERGY_SMEM);

    wconv_kernel<<<128, 256>>>(Wh, Wd);
    energy_hmma_kernel<<<BT / 128, 128, ENERGY_SMEM>>>(Hp, Hd, Wa, alpha);
    softmax_kernel<<<B_DIM, 1024>>>(accw, ba, beta, alpha);
    context_part_kernel<<<B_DIM * 8, 256>>>(alpha);
    context_reduce_kernel<<<16, 1024>>>(ctx);
}

// round 12
// speedup vs baseline: 1.0011x; 1.0011x over previous
#include <cuda_runtime.h>
#include <cuda_fp16.h>
#include <cstdint>
#include <math.h>

// Problem shape (fixed by reference): B=128, T=2048, H=128
#define B_DIM 128
#define T_DIM 2048
#define H_DIM 128
#define BT (B_DIM * T_DIM)

#define SW128(off) ((off) ^ (((off) >> 3) & 0x70))

__device__ __forceinline__ uint32_t smem_to_u32(const void* p) {
    uint32_t a;
    asm("{ .reg .u64 t; cvta.to.shared.u64 t, %1; cvt.u32.u64 %0, t; }"
        : "=r"(a) : "l"(p));
    return a;
}

__device__ __forceinline__ void ldsm4(uint32_t* r, uint32_t addr) {
    asm volatile("ldmatrix.sync.aligned.m8n8.x4.shared.b16 {%0,%1,%2,%3}, [%4];"
                 : "=r"(r[0]), "=r"(r[1]), "=r"(r[2]), "=r"(r[3]) : "r"(addr));
}

// mma m16n8k16 row.col f32.f16.f16.f32
__device__ __forceinline__ void mma_f16(float* c, const uint32_t* a,
                                        uint32_t b0, uint32_t b1) {
    asm volatile(
        "mma.sync.aligned.m16n8k16.row.col.f32.f16.f16.f32 "
        "{%0,%1,%2,%3}, {%4,%5,%6,%7}, {%8,%9}, {%0,%1,%2,%3};"
        : "+f"(c[0]), "+f"(c[1]), "+f"(c[2]), "+f"(c[3])
        : "r"(a[0]), "r"(a[1]), "r"(a[2]), "r"(a[3]), "r"(b0), "r"(b1));
}

__device__ __forceinline__ float tanh_fast(float z) {
    const float ex = __expf(2.f * z);
    return 1.f - __fdividef(2.f, ex + 1.f);
}

// ---------------------------------------------------------------------------
// Pre-converted weights: 4 K-chunks; each = one SW128 fp16 tile [128 o][64 k].
// ---------------------------------------------------------------------------
__device__ __align__(16) unsigned char g_Wimg[4 * 16384];
__device__ float g_ctxp[8 * B_DIM * H_DIM];   // context partials [part][b][h]

__global__ __launch_bounds__(256) void wconv_kernel(
    const float* __restrict__ Wh, const float* __restrict__ Wd)
{
    const int idx = blockIdx.x * 256 + threadIdx.x;   // 32768 total
    const int ch  = idx >> 13;
    const int rem = idx & 8191;
    const int o   = rem >> 6;
    const int kc  = rem & 63;
    const float* src = (ch < 2) ? Wh : Wd;
    const float x = src[o * 128 + (ch & 1) * 64 + kc];
    const uint32_t sw = SW128((uint32_t)(o * 128 + kc * 2));
    *(__half*)(g_Wimg + ch * 16384 + sw) = __float2half_rn(x);
}

// ---------------------------------------------------------------------------
// Energy kernel (HMMA fp16, single pass, M-tile 256).
// CTA = 256 threads (8 warps), M-tile 256 rows x N=128, K=256 in 4 chunks
// of 64. Warp (wy,wx): rows wy*64..+64, cols wx*64..+64 (wy 0..3, wx 0..1).
// z = X16 * W16 (fp32 accum); energy[row] = sum_n Wa[n] * tanh(z[row,n]).
// Simple sync staging (proven R7 pattern); B tile amortized over 2x rows.
// ---------------------------------------------------------------------------
#define A_X  2048
#define B_W  (2048 + 32768)
#define ENERGY_SMEM (2048 + 32768 + 16384 + 1024)

__global__ __launch_bounds__(256) void energy_hmma_kernel(
    const float* __restrict__ Hp, const float* __restrict__ Hd,
    const float* __restrict__ Wa, float* __restrict__ energy)
{
    extern __shared__ char dsmem[];
    const uint32_t raw  = smem_to_u32(dsmem);
    const uint32_t base = (raw + 1023) & ~1023u;
    char* basep = dsmem + (base - raw);

    float* esum = (float*)(basep);           // [0,1024): per-row energy (256)
    float* wa_s = (float*)(basep + 1024);    // [1024,1536): W_a copy

    const int tid  = threadIdx.x;
    const int lane = tid & 31;
    const int wid  = tid >> 5;
    const int wy   = wid >> 1;               // row quarter (0..3)
    const int wx   = wid & 1;                // col half (0..1)
    const int row0 = blockIdx.x * 256;

    if (tid < 128) wa_s[tid] = Wa[tid];

    const int q  = lane >> 3;
    const int l7 = lane & 7;
    const uint32_t offA0 = (uint32_t)((wy * 64 + l7 + (q & 1) * 8) * 128 + (q >> 1) * 16);
    const uint32_t offB0 = (uint32_t)((wx * 64 + l7 + (q >> 1) * 8) * 128 + (q & 1) * 16);
    const uint32_t baseA = base + A_X;
    const uint32_t baseB = base + B_W;

    // X staging map: 16 threads per row (fully coalesced 256B rows)
    const int srow = tid >> 4;               // 0..15
    const int scol = (tid & 15) * 4;         // 0..60

    float acc[4][8][4];
    #pragma unroll
    for (int mt = 0; mt < 4; ++mt)
        #pragma unroll
        for (int nt = 0; nt < 8; ++nt)
            #pragma unroll
            for (int j = 0; j < 4; ++j) acc[mt][nt][j] = 0.f;

    #pragma unroll 1
    for (int ch = 0; ch < 4; ++ch) {
        __syncthreads();   // prior compute done before overwriting tiles

        // --- stage W tile (pre-swizzled fp16 image; L2-hot) ---
        const uint4* wsrc = (const uint4*)(g_Wimg + (size_t)ch * 16384);
        uint4* bw = (uint4*)(basep + B_W);
        #pragma unroll
        for (int i = 0; i < 4; ++i)
            bw[tid + i * 256] = wsrc[tid + i * 256];

        // --- stage X tile (256 rows): fp32 -> fp16, SW128 swizzled ---
        const float* xsrc = ((ch < 2) ? Hp : Hd) + (ch & 1) * 64;
        #pragma unroll
        for (int it = 0; it < 16; ++it) {
            const int r = it * 16 + srow;
            const float4 v = *(const float4*)(xsrc + ((size_t)(row0 + r) << 7) + scol);
            const __half2 h0 = __floats2half2_rn(v.x, v.y);
            const __half2 h1 = __floats2half2_rn(v.z, v.w);
            const uint32_t sw = SW128((uint32_t)(r * 128 + scol * 2));
            uint2 hi2;
            hi2.x = *(const uint32_t*)&h0;  hi2.y = *(const uint32_t*)&h1;
            *(uint2*)(basep + A_X + sw) = hi2;
        }
        __syncthreads();

        // --- compute: 4 k-steps of 16, single pass ---
        #pragma unroll 1
        for (int ks = 0; ks < 4; ++ks) {
            const uint32_t ks32 = ks * 32;
            uint32_t br[4][4], a[4][4];
            #pragma unroll
            for (int p = 0; p < 4; ++p)
                ldsm4(br[p], baseB + SW128(offB0 + p * 2048 + ks32));
            #pragma unroll
            for (int mt = 0; mt < 4; ++mt)
                ldsm4(a[mt], baseA + SW128(offA0 + mt * 2048 + ks32));
            #pragma unroll
            for (int mt = 0; mt < 4; ++mt)
                #pragma unroll
                for (int nt = 0; nt < 8; ++nt)
                    mma_f16(acc[mt][nt], a[mt],
                            br[nt >> 1][(nt & 1) * 2], br[nt >> 1][(nt & 1) * 2 + 1]);
        }
    }

    // --- epilogue ---
    float wa_r[16];
    #pragma unroll
    for (int nt = 0; nt < 8; ++nt) {
        wa_r[nt * 2 + 0] = wa_s[wx * 64 + nt * 8 + (lane & 3) * 2 + 0];
        wa_r[nt * 2 + 1] = wa_s[wx * 64 + nt * 8 + (lane & 3) * 2 + 1];
    }
    __syncthreads();
    esum[tid] = 0.f;
    __syncthreads();

    #pragma unroll
    for (int mt = 0; mt < 4; ++mt) {
        #pragma unroll
        for (int half = 0; half < 2; ++half) {
            float p = 0.f;
            #pragma unroll
            for (int nt = 0; nt < 8; ++nt) {
                p += wa_r[nt * 2 + 0] * tanh_fast(acc[mt][nt][half * 2 + 0]);
                p += wa_r[nt * 2 + 1] * tanh_fast(acc[mt][nt][half * 2 + 1]);
            }
            p += __shfl_xor_sync(0xffffffffu, p, 1);
            p += __shfl_xor_sync(0xffffffffu, p, 2);
            if ((lane & 3) == 0)
                atomicAdd(&esum[wy * 64 + mt * 16 + half * 8 + (lane >> 2)], p);
        }
    }
    __syncthreads();
    energy[row0 + tid] = esum[tid];
}

// ---------------------------------------------------------------------------
// Softmax: 1024 threads, 2 elems/thread, register-resident, shuffle reductions.
// ---------------------------------------------------------------------------
__device__ __forceinline__ float warp_max(float v) {
    #pragma unroll
    for (int m = 16; m > 0; m >>= 1)
        v = fmaxf(v, __shfl_xor_sync(0xffffffffu, v, m));
    return v;
}
__device__ __forceinline__ float warp_sum(float v) {
    #pragma unroll
    for (int m = 16; m > 0; m >>= 1)
        v += __shfl_xor_sync(0xffffffffu, v, m);
    return v;
}
__device__ __forceinline__ float block_red(float v, float* red, int tid, bool is_max) {
    v = is_max ? warp_max(v) : warp_sum(v);
    if ((tid & 31) == 0) red[tid >> 5] = v;
    __syncthreads();
    if (tid < 32) {
        float w = red[tid];
        w = is_max ? warp_max(w) : warp_sum(w);
        if (tid == 0) red[0] = w;
    }
    __syncthreads();
    float r = red[0];
    __syncthreads();
    return r;
}

__global__ __launch_bounds__(1024) void softmax_kernel(
    const float* __restrict__ acc_w, const float* __restrict__ ba_p,
    const float* __restrict__ beta_p, float* __restrict__ alpha)
{
    const int b = blockIdx.x;
    const int tid = threadIdx.x;
    __shared__ float red[32];

    const float* aw = acc_w + (size_t)b * T_DIM;
    float* al = alpha + (size_t)b * T_DIM;

    const float a0 = aw[tid], a1 = aw[tid + 1024];
    const float e0 = al[tid], e1 = al[tid + 1024];

    const float denom = fmaxf(block_red(fmaxf(a0, a1), red, tid, true), 1e-6f);

    const float beta = *beta_p;
    const float bpos = fmaxf(beta, 0.f) + log1pf(expf(-fabsf(beta)));
    const float ba = *ba_p;
    const float inv_d = bpos / denom;

    const float s0 = (e0 + ba) * (1.f + inv_d * a0);
    const float s1 = (e1 + ba) * (1.f + inv_d * a1);

    const float smax = block_red(fmaxf(s0, s1), red, tid, true);
    const float p0 = expf(s0 - smax);
    const float p1 = expf(s1 - smax);
    const float inv = 1.f / block_red(p0 + p1, red, tid, false);

    al[tid]        = p0 * inv;
    al[tid + 1024] = p1 * inv;
}

// ---------------------------------------------------------------------------
// Context stage 1: grid = B*8 (b x 8 T-parts), 256 threads = 8 warps.
// Lane l covers h = 4l..4l+3 (float4); warp w covers t-slice part*256+w*32.
// ---------------------------------------------------------------------------
__global__ __launch_bounds__(256) void context_part_kernel(
    const float* __restrict__ Hp, const float* __restrict__ alpha)
{
    const int bid  = blockIdx.x;
    const int b    = bid >> 3;
    const int part = bid & 7;
    const int tid  = threadIdx.x;
    const int lane = tid & 31;
    const int w    = tid >> 5;            // 0..7

    const float* al = alpha + (size_t)b * T_DIM;
    const float* hp = Hp + ((size_t)b * T_DIM) * H_DIM + lane * 4;

    const int t0 = part * 256 + w * 32;
    float4 acc = make_float4(0.f, 0.f, 0.f, 0.f);
    #pragma unroll 8
    for (int t = 0; t < 32; ++t) {
        const float a = al[t0 + t];
        const float4 v = *(const float4*)(hp + (size_t)(t0 + t) * H_DIM);
        acc.x += a * v.x; acc.y += a * v.y;
        acc.z += a * v.z; acc.w += a * v.w;
    }

    __shared__ float cbuf[8 * 128];
    *(float4*)&cbuf[w * 128 + lane * 4] = acc;
    __syncthreads();

    if (tid < 128) {
        float s = 0.f;
        #pragma unroll
        for (int j = 0; j < 8; ++j) s += cbuf[j * 128 + tid];
        g_ctxp[(part * B_DIM + b) * H_DIM + tid] = s;
    }
}

__global__ __launch_bounds__(1024) void context_reduce_kernel(float* __restrict__ ctx)
{
    const int i = blockIdx.x * 1024 + threadIdx.x;   // 16384 total
    float s = 0.f;
    #pragma unroll
    for (int p = 0; p < 8; ++p) s += g_ctxp[p * 16384 + i];
    ctx[i] = s;
}

// ---------------------------------------------------------------------------
// Launch. Inputs per metadata order:
//   0 H_pos, 1 H_dyn, 2 acc_w, 3 W_h, 4 W_d, 5 W_a, 6 b_a, 7 beta
// Output: context [B,H] then alpha [B,T]. Energy staged in the alpha region.
// ---------------------------------------------------------------------------
extern "C" void kernel_launch(void* const* d_in, const int* in_sizes, int n_in,
                              void* d_out, int out_size)
{
    const float* Hp   = (const float*)d_in[0];
    const float* Hd   = (const float*)d_in[1];
    const float* accw = (const float*)d_in[2];
    const float* Wh   = (const float*)d_in[3];
    const float* Wd   = (const float*)d_in[4];
    const float* Wa   = (const float*)d_in[5];
    const float* ba   = (const float*)d_in[6];
    const float* beta = (const float*)d_in[7];

    float* out   = (float*)d_out;
    float* ctx   = out;                    // [B, H]
    float* alpha = out + B_DIM * H_DIM;    // [B, T]

    cudaFuncSetAttribute(energy_hmma_kernel,
                         cudaFuncAttributeMaxDynamicSharedMemorySize, ENERGY_SMEM);

    wconv_kernel<<<128, 256>>>(Wh, Wd);
    energy_hmma_kernel<<<BT / 256, 256, ENERGY_SMEM>>>(Hp, Hd, Wa, alpha);
    softmax_kernel<<<B_DIM, 1024>>>(accw, ba, beta, alpha);
    context_part_kernel<<<B_DIM * 8, 256>>>(Hp, alpha);
    context_reduce_kernel<<<16, 1024>>>(ctx);
}

// round 14
// speedup vs baseline: 1.3546x; 1.3532x over previous
#include <cuda_runtime.h>
#include <cuda_fp16.h>
#include <cstdint>
#include <math.h>

// Problem shape (fixed by reference): B=128, T=2048, H=128
#define B_DIM 128
#define T_DIM 2048
#define H_DIM 128
#define BT (B_DIM * T_DIM)

#define SW128(off) ((off) ^ (((off) >> 3) & 0x70))

__device__ __forceinline__ uint32_t smem_to_u32(const void* p) {
    uint32_t a;
    asm("{ .reg .u64 t; cvta.to.shared.u64 t, %1; cvt.u32.u64 %0, t; }"
        : "=r"(a) : "l"(p));
    return a;
}

__device__ __forceinline__ void ldsm4(uint32_t* r, uint32_t addr) {
    asm volatile("ldmatrix.sync.aligned.m8n8.x4.shared.b16 {%0,%1,%2,%3}, [%4];"
                 : "=r"(r[0]), "=r"(r[1]), "=r"(r[2]), "=r"(r[3]) : "r"(addr));
}

// mma m16n8k16 row.col f32.f16.f16.f32
__device__ __forceinline__ void mma_f16(float* c, const uint32_t* a,
                                        uint32_t b0, uint32_t b1) {
    asm volatile(
        "mma.sync.aligned.m16n8k16.row.col.f32.f16.f16.f32 "
        "{%0,%1,%2,%3}, {%4,%5,%6,%7}, {%8,%9}, {%0,%1,%2,%3};"
        : "+f"(c[0]), "+f"(c[1]), "+f"(c[2]), "+f"(c[3])
        : "r"(a[0]), "r"(a[1]), "r"(a[2]), "r"(a[3]), "r"(b0), "r"(b1));
}

__device__ __forceinline__ float tanh_fast(float z) {
    const float ex = __expf(2.f * z);
    return 1.f - __fdividef(2.f, ex + 1.f);
}

// ---------------------------------------------------------------------------
// Pre-converted weights: 4 sequential 16KB SW128 fp16 subtiles
// (Wh k0-63, Wh k64-127, Wd k0-63, Wd k64-127) — i.e. two 32KB big chunks.
// ---------------------------------------------------------------------------
__device__ __align__(16) unsigned char g_Wimg[4 * 16384];
__device__ float g_ctxp[8 * B_DIM * H_DIM];   // context partials [part][b][h]

__global__ __launch_bounds__(256) void wconv_kernel(
    const float* __restrict__ Wh, const float* __restrict__ Wd)
{
    const int idx = blockIdx.x * 256 + threadIdx.x;   // 32768 total
    const int ch  = idx >> 13;
    const int rem = idx & 8191;
    const int o   = rem >> 6;
    const int kc  = rem & 63;
    const float* src = (ch < 2) ? Wh : Wd;
    const float x = src[o * 128 + (ch & 1) * 64 + kc];
    const uint32_t sw = SW128((uint32_t)(o * 128 + kc * 2));
    *(__half*)(g_Wimg + ch * 16384 + sw) = __float2half_rn(x);
}

// ---------------------------------------------------------------------------
// Energy kernel (HMMA fp16, single pass, 2 big K-chunks of 128).
// CTA = 128 threads (4 warps), M-tile 128 x N=128.
// Big chunk bc: X = (bc ? Hd : Hp) full K=128; A/B regions each hold two
// contiguous 16KB SW128 subtiles (k0-63, k64-127).
// z = X16 * W16 (fp32 accum); energy[row] = sum_n Wa[n] * tanh(z[row,n]).
// ---------------------------------------------------------------------------
#define A_X  1024
#define B_W  (1024 + 32768)
#define ENERGY_SMEM (1024 + 65536 + 1024)

__global__ __launch_bounds__(128) void energy_hmma_kernel(
    const float* __restrict__ Hp, const float* __restrict__ Hd,
    const float* __restrict__ Wa, float* __restrict__ energy)
{
    extern __shared__ char dsmem[];
    const uint32_t raw  = smem_to_u32(dsmem);
    const uint32_t base = (raw + 1023) & ~1023u;
    char* basep = dsmem + (base - raw);

    float* esum = (float*)(basep);          // [0,512): per-row energy
    float* wa_s = (float*)(basep + 512);    // [512,1024): W_a copy

    const int tid  = threadIdx.x;
    const int lane = tid & 31;
    const int wid  = tid >> 5;
    const int wy   = wid >> 1;              // row half
    const int wx   = wid & 1;               // col half
    const int row0 = blockIdx.x * 128;

    wa_s[tid & 127] = Wa[tid & 127];

    const int q  = lane >> 3;
    const int l7 = lane & 7;
    const uint32_t offA0 = (uint32_t)((wy * 64 + l7 + (q & 1) * 8) * 128 + (q >> 1) * 16);
    const uint32_t offB0 = (uint32_t)((wx * 64 + l7 + (q >> 1) * 8) * 128 + (q & 1) * 16);
    const uint32_t baseA = base + A_X;
    const uint32_t baseB = base + B_W;

    // X staging map: 16 threads per row (fully coalesced 256B half-rows)
    const int srow = tid >> 4;              // 0..7
    const int scol = (tid & 15) * 4;        // 0..60

    float acc[4][8][4];
    #pragma unroll
    for (int mt = 0; mt < 4; ++mt)
        #pragma unroll
        for (int nt = 0; nt < 8; ++nt)
            #pragma unroll
            for (int j = 0; j < 4; ++j) acc[mt][nt][j] = 0.f;

    #pragma unroll 1
    for (int bc = 0; bc < 2; ++bc) {
        __syncthreads();   // prior compute done before overwriting tiles

        // --- stage B big chunk: 32KB linear copy (pre-swizzled; L2-hot) ---
        const uint4* wsrc = (const uint4*)(g_Wimg + (size_t)bc * 32768);
        uint4* bw = (uint4*)(basep + B_W);
        #pragma unroll
        for (int i = 0; i < 16; ++i)
            bw[tid + i * 128] = wsrc[tid + i * 128];

        // --- stage X big chunk: 128 rows x 128 k, fp32 -> fp16, SW128 ---
        const float* xsrc = bc ? Hd : Hp;
        #pragma unroll
        for (int it = 0; it < 16; ++it) {
            const int r = it * 8 + srow;
            const float* xrow = xsrc + ((size_t)(row0 + r) << 7);
            #pragma unroll
            for (int h = 0; h < 2; ++h) {
                const float4 v = *(const float4*)(xrow + h * 64 + scol);
                const __half2 h0 = __floats2half2_rn(v.x, v.y);
                const __half2 h1 = __floats2half2_rn(v.z, v.w);
                const uint32_t sw = SW128((uint32_t)(r * 128 + scol * 2));
                uint2 hi2;
                hi2.x = *(const uint32_t*)&h0;  hi2.y = *(const uint32_t*)&h1;
                *(uint2*)(basep + A_X + h * 16384 + sw) = hi2;
            }
        }
        __syncthreads();

        // --- compute: 8 k-steps of 16 (two 16KB subtiles), single pass ---
        #pragma unroll 1
        for (int ks = 0; ks < 8; ++ks) {
            const uint32_t sub  = (uint32_t)(ks >> 2) * 16384;
            const uint32_t ks32 = (ks & 3) * 32;
            uint32_t br[4][4], a[4][4];
            #pragma unroll
            for (int p = 0; p < 4; ++p)
                ldsm4(br[p], baseB + sub + SW128(offB0 + p * 2048 + ks32));
            #pragma unroll
            for (int mt = 0; mt < 4; ++mt)
                ldsm4(a[mt], baseA + sub + SW128(offA0 + mt * 2048 + ks32));
            #pragma unroll
            for (int mt = 0; mt < 4; ++mt)
                #pragma unroll
                for (int nt = 0; nt < 8; ++nt)
                    mma_f16(acc[mt][nt], a[mt],
                            br[nt >> 1][(nt & 1) * 2], br[nt >> 1][(nt & 1) * 2 + 1]);
        }
    }

    // --- epilogue ---
    float wa_r[16];
    #pragma unroll
    for (int nt = 0; nt < 8; ++nt) {
        wa_r[nt * 2 + 0] = wa_s[wx * 64 + nt * 8 + (lane & 3) * 2 + 0];
        wa_r[nt * 2 + 1] = wa_s[wx * 64 + nt * 8 + (lane & 3) * 2 + 1];
    }
    __syncthreads();
    esum[tid & 127] = 0.f;
    __syncthreads();

    #pragma unroll
    for (int mt = 0; mt < 4; ++mt) {
        #pragma unroll
        for (int half = 0; half < 2; ++half) {
            float p = 0.f;
            #pragma unroll
            for (int nt = 0; nt < 8; ++nt) {
                p += wa_r[nt * 2 + 0] * tanh_fast(acc[mt][nt][half * 2 + 0]);
                p += wa_r[nt * 2 + 1] * tanh_fast(acc[mt][nt][half * 2 + 1]);
            }
            p += __shfl_xor_sync(0xffffffffu, p, 1);
            p += __shfl_xor_sync(0xffffffffu, p, 2);
            if ((lane & 3) == 0)
                atomicAdd(&esum[wy * 64 + mt * 16 + half * 8 + (lane >> 2)], p);
        }
    }
    __syncthreads();
    energy[row0 + tid] = esum[tid];
}

// ---------------------------------------------------------------------------
// Softmax: 1024 threads, 2 elems/thread, register-resident, shuffle reductions.
// ---------------------------------------------------------------------------
__device__ __forceinline__ float warp_max(float v) {
    #pragma unroll
    for (int m = 16; m > 0; m >>= 1)
        v = fmaxf(v, __shfl_xor_sync(0xffffffffu, v, m));
    return v;
}
__device__ __forceinline__ float warp_sum(float v) {
    #pragma unroll
    for (int m = 16; m > 0; m >>= 1)
        v += __shfl_xor_sync(0xffffffffu, v, m);
    return v;
}
__device__ __forceinline__ float block_red(float v, float* red, int tid, bool is_max) {
    v = is_max ? warp_max(v) : warp_sum(v);
    if ((tid & 31) == 0) red[tid >> 5] = v;
    __syncthreads();
    if (tid < 32) {
        float w = red[tid];
        w = is_max ? warp_max(w) : warp_sum(w);
        if (tid == 0) red[0] = w;
    }
    __syncthreads();
    float r = red[0];
    __syncthreads();
    return r;
}

__global__ __launch_bounds__(1024) void softmax_kernel(
    const float* __restrict__ acc_w, const float* __restrict__ ba_p,
    const float* __restrict__ beta_p, float* __restrict__ alpha)
{
    const int b = blockIdx.x;
    const int tid = threadIdx.x;
    __shared__ float red[32];

    const float* aw = acc_w + (size_t)b * T_DIM;
    float* al = alpha + (size_t)b * T_DIM;

    const float a0 = aw[tid], a1 = aw[tid + 1024];
    const float e0 = al[tid], e1 = al[tid + 1024];

    const float denom = fmaxf(block_red(fmaxf(a0, a1), red, tid, true), 1e-6f);

    const float beta = *beta_p;
    const float bpos = fmaxf(beta, 0.f) + log1pf(expf(-fabsf(beta)));
    const float ba = *ba_p;
    const float inv_d = bpos / denom;

    const float s0 = (e0 + ba) * (1.f + inv_d * a0);
    const float s1 = (e1 + ba) * (1.f + inv_d * a1);

    const float smax = block_red(fmaxf(s0, s1), red, tid, true);
    const float p0 = expf(s0 - smax);
    const float p1 = expf(s1 - smax);
    const float inv = 1.f / block_red(p0 + p1, red, tid, false);

    al[tid]        = p0 * inv;
    al[tid + 1024] = p1 * inv;
}

// ---------------------------------------------------------------------------
// Context stage 1: grid = B*8 (b x 8 T-parts), 256 threads = 8 warps.
// ---------------------------------------------------------------------------
__global__ __launch_bounds__(256) void context_part_kernel(
    const float* __restrict__ Hp, const float* __restrict__ alpha)
{
    const int bid  = blockIdx.x;
    const int b    = bid >> 3;
    const int part = bid & 7;
    const int tid  = threadIdx.x;
    const int lane = tid & 31;
    const int w    = tid >> 5;            // 0..7

    const float* al = alpha + (size_t)b * T_DIM;
    const float* hp = Hp + ((size_t)b * T_DIM) * H_DIM + lane * 4;

    const int t0 = part * 256 + w * 32;
    float4 acc = make_float4(0.f, 0.f, 0.f, 0.f);
    #pragma unroll 8
    for (int t = 0; t < 32; ++t) {
        const float a = al[t0 + t];
        const float4 v = *(const float4*)(hp + (size_t)(t0 + t) * H_DIM);
        acc.x += a * v.x; acc.y += a * v.y;
        acc.z += a * v.z; acc.w += a * v.w;
    }

    __shared__ float cbuf[8 * 128];
    *(float4*)&cbuf[w * 128 + lane * 4] = acc;
    __syncthreads();

    if (tid < 128) {
        float s = 0.f;
        #pragma unroll
        for (int j = 0; j < 8; ++j) s += cbuf[j * 128 + tid];
        g_ctxp[(part * B_DIM + b) * H_DIM + tid] = s;
    }
}

__global__ __launch_bounds__(1024) void context_reduce_kernel(float* __restrict__ ctx)
{
    const int i = blockIdx.x * 1024 + threadIdx.x;   // 16384 total
    float s = 0.f;
    #pragma unroll
    for (int p = 0; p < 8; ++p) s += g_ctxp[p * 16384 + i];
    ctx[i] = s;
}

// ---------------------------------------------------------------------------
// Launch. Inputs per metadata order:
//   0 H_pos, 1 H_dyn, 2 acc_w, 3 W_h, 4 W_d, 5 W_a, 6 b_a, 7 beta
// Output: context [B,H] then alpha [B,T]. Energy staged in the alpha region.
// ---------------------------------------------------------------------------
extern "C" void kernel_launch(void* const* d_in, const int* in_sizes, int n_in,
                              void* d_out, int out_size)
{
    const float* Hp   = (const float*)d_in[0];
    const float* Hd   = (const float*)d_in[1];
    const float* accw = (const float*)d_in[2];
    const float* Wh   = (const float*)d_in[3];
    const float* Wd   = (const float*)d_in[4];
    const float* Wa   = (const float*)d_in[5];
    const float* ba   = (const float*)d_in[6];
    const float* beta = (const float*)d_in[7];

    float* out   = (float*)d_out;
    float* ctx   = out;                    // [B, H]
    float* alpha = out + B_DIM * H_DIM;    // [B, T]

    cudaFuncSetAttribute(energy_hmma_kernel,
                         cudaFuncAttributeMaxDynamicSharedMemorySize, ENERGY_SMEM);

    wconv_kernel<<<128, 256>>>(Wh, Wd);
    energy_hmma_kernel<<<BT / 128, 128, ENERGY_SMEM>>>(Hp, Hd, Wa, alpha);
    softmax_kernel<<<B_DIM, 1024>>>(accw, ba, beta, alpha);
    context_part_kernel<<<B_DIM * 8, 256>>>(Hp, alpha);
    context_reduce_kernel<<<16, 1024>>>(ctx);
}